// round 5
// baseline (speedup 1.0000x reference)
#include <cuda_runtime.h>
#include <cstdint>

// NodePropagatorSparse: out[b,e,0:256]   = node_states[b, edge_src[e], :]
//                       out[b,e,256:512] = node_states[b, edge_tgt[e], :]
// B=4, N=10000, E=160000, D=256. node_states fp32, indices int32 (JAX x64-off).
//
// R5: 256-bit gather loads with L2::evict_last (sm_103 requires .v4.b64 for
// the hint) pin the 41MB node_states set in L2; .cs streaming stores keep the
// 1.31GB output stream evict-first. 2 edges per 128-thread block.

#define B_DIM 4
#define N_DIM 10000
#define E_DIM 160000
#define D_DIM 256
#define D8    (D_DIM / 8)        // 32 x 32B chunks per D-row
#define ROW8  (2 * D8)           // 64 x 32B chunks per output (b,e) row

struct V32 { unsigned long long a, b, c, d; };   // 32 bytes

__device__ __forceinline__ V32 ldg_evict_last_32(const V32* p) {
    V32 v;
    asm volatile("ld.global.L2::evict_last.v4.b64 {%0,%1,%2,%3}, [%4];"
                 : "=l"(v.a), "=l"(v.b), "=l"(v.c), "=l"(v.d)
                 : "l"(p));
    return v;
}

__device__ __forceinline__ void stcs_32(V32* p, V32 v) {
    asm volatile("st.global.cs.v4.b64 [%0], {%1,%2,%3,%4};"
                 :: "l"(p), "l"(v.a), "l"(v.b), "l"(v.c), "l"(v.d)
                 : "memory");
}

__global__ __launch_bounds__(128, 16)
void node_prop_gather_kernel(const V32* __restrict__ ns,    // [B, N, D8]
                             const int* __restrict__ src,   // [E] int32
                             const int* __restrict__ tgt,   // [E] int32
                             V32* __restrict__ out)         // [B, E, ROW8]
{
    const int t = threadIdx.x;                    // 0..127
    const int e = blockIdx.x * 2 + (t >> 6);      // 2 edges per block
    const int half = (t >> 5) & 1;                // 0 = src half, 1 = tgt half
    const int col  = t & 31;                      // 32B column within the D-row

    const int idx = half ? tgt[e] : src[e];       // broadcast load per warp

    const V32* src_row = ns  + (size_t)idx * D8 + col;             // b=0
    V32*       dst     = out + (size_t)e * ROW8 + half * D8 + col;

    // b-loop unrolled: 4 independent 32B loads, L2 evict-last (pin working set)
    V32 v0 = ldg_evict_last_32(src_row + 0 * (size_t)N_DIM * D8);
    V32 v1 = ldg_evict_last_32(src_row + 1 * (size_t)N_DIM * D8);
    V32 v2 = ldg_evict_last_32(src_row + 2 * (size_t)N_DIM * D8);
    V32 v3 = ldg_evict_last_32(src_row + 3 * (size_t)N_DIM * D8);

    // Streaming 32B stores: evict-first in L2.
    stcs_32(dst + 0 * (size_t)E_DIM * ROW8, v0);
    stcs_32(dst + 1 * (size_t)E_DIM * ROW8, v1);
    stcs_32(dst + 2 * (size_t)E_DIM * ROW8, v2);
    stcs_32(dst + 3 * (size_t)E_DIM * ROW8, v3);
}

extern "C" void kernel_launch(void* const* d_in, const int* in_sizes, int n_in,
                              void* d_out, int out_size)
{
    const V32* ns   = (const V32*)d_in[0];
    const int* src  = (const int*)d_in[1];
    const int* tgt  = (const int*)d_in[2];
    V32*       out  = (V32*)d_out;

    node_prop_gather_kernel<<<E_DIM / 2, 128>>>(ns, src, tgt, out);
}

// round 6
// speedup vs baseline: 1.2638x; 1.2638x over previous
#include <cuda_runtime.h>
#include <cstdint>

// NodePropagatorSparse: out[b,e,0:256]   = node_states[b, edge_src[e], :]
//                       out[b,e,256:512] = node_states[b, edge_tgt[e], :]
// B=4, N=10000, E=160000, D=256. node_states fp32, indices int32 (JAX x64-off).
//
// R6: batch-phased execution. blockIdx.y = b, so CTAs of the same batch run as
// a temporal wave -> per-phase gather working set is 10.24MB (one batch slice),
// easily L2-resident. Plain loads (R5 showed evict_last thrashes its L2
// partition); __stcs evict-first streaming stores (R3 win).

#define B_DIM 4
#define N_DIM 10000
#define E_DIM 160000
#define D_DIM 256
#define D4    (D_DIM / 4)        // 64 float4 per D-row
#define ROW4  (2 * D4)           // 128 float4 per output (b,e) row

__global__ __launch_bounds__(256, 8)
void node_prop_gather_kernel(const float4* __restrict__ ns4,   // [B, N, D4]
                             const int* __restrict__ src,      // [E] int32
                             const int* __restrict__ tgt,      // [E] int32
                             float4* __restrict__ out4)        // [B, E, ROW4]
{
    const int t = threadIdx.x;                    // 0..255
    const int e = blockIdx.x * 2 + (t >> 7);      // 2 edges per block
    const int b = blockIdx.y;                     // batch phase
    const int half = (t >> 6) & 1;                // 0 = src half, 1 = tgt half
    const int col  = t & 63;                      // float4 column within D-row

    const int idx = half ? tgt[e] : src[e];       // broadcast load per warp-pair

    const float4 v = ns4[((size_t)b * N_DIM + idx) * D4 + col];

    __stcs(&out4[((size_t)b * E_DIM + e) * ROW4 + half * D4 + col], v);
}

extern "C" void kernel_launch(void* const* d_in, const int* in_sizes, int n_in,
                              void* d_out, int out_size)
{
    const float4* ns4  = (const float4*)d_in[0];
    const int*    src  = (const int*)d_in[1];
    const int*    tgt  = (const int*)d_in[2];
    float4*       out4 = (float4*)d_out;

    dim3 grid(E_DIM / 2, B_DIM);
    node_prop_gather_kernel<<<grid, 256>>>(ns4, src, tgt, out4);
}

// round 7
// speedup vs baseline: 1.6003x; 1.2662x over previous
#include <cuda_runtime.h>
#include <cstdint>

// NodePropagatorSparse: out[b,e,0:256]   = node_states[b, edge_src[e], :]
//                       out[b,e,256:512] = node_states[b, edge_tgt[e], :]
// B=4, N=10000, E=160000, D=256. node_states fp32, indices int32 (JAX x64-off).
//
// R7: batch phasing (blockIdx.y=b keeps per-phase gather set at 10.24MB,
// L2-resident; fixed the DRAM read excess in R6) + edge-unroll x4 per thread
// to restore MLP=4 (R6 was issue/latency-limited at MLP=1).
// __stcs evict-first streaming stores throughout.

#define B_DIM 4
#define N_DIM 10000
#define E_DIM 160000
#define D_DIM 256
#define D4    (D_DIM / 4)        // 64 float4 per D-row
#define ROW4  (2 * D4)           // 128 float4 per output (b,e) row
#define EDGES_PER_BLOCK 8

__global__ __launch_bounds__(256, 8)
void node_prop_gather_kernel(const float4* __restrict__ ns4,   // [B, N, D4]
                             const int* __restrict__ src,      // [E] int32
                             const int* __restrict__ tgt,      // [E] int32
                             float4* __restrict__ out4)        // [B, E, ROW4]
{
    const int t    = threadIdx.x;                 // 0..255
    const int b    = blockIdx.y;                  // batch phase
    const int half = (t >> 6) & 1;                // 0 = src half, 1 = tgt half
    const int col  = t & 63;                      // float4 column within D-row
    const int esub = t >> 7;                      // 0..1: edge-within-pair

    const int e0 = blockIdx.x * EDGES_PER_BLOCK + esub;
    const int* iarr = half ? tgt : src;

    const float4* nsb = ns4 + (size_t)b * ((size_t)N_DIM * D4) + col;
    float4* outb = out4 + (size_t)b * ((size_t)E_DIM * ROW4) + half * D4 + col;

    // 4 independent (edge) gathers -> MLP=4
    const int i0 = iarr[e0 + 0];
    const int i1 = iarr[e0 + 2];
    const int i2 = iarr[e0 + 4];
    const int i3 = iarr[e0 + 6];

    float4 v0 = nsb[(size_t)i0 * D4];
    float4 v1 = nsb[(size_t)i1 * D4];
    float4 v2 = nsb[(size_t)i2 * D4];
    float4 v3 = nsb[(size_t)i3 * D4];

    __stcs(&outb[(size_t)(e0 + 0) * ROW4], v0);
    __stcs(&outb[(size_t)(e0 + 2) * ROW4], v1);
    __stcs(&outb[(size_t)(e0 + 4) * ROW4], v2);
    __stcs(&outb[(size_t)(e0 + 6) * ROW4], v3);
}

extern "C" void kernel_launch(void* const* d_in, const int* in_sizes, int n_in,
                              void* d_out, int out_size)
{
    const float4* ns4  = (const float4*)d_in[0];
    const int*    src  = (const int*)d_in[1];
    const int*    tgt  = (const int*)d_in[2];
    float4*       out4 = (float4*)d_out;

    dim3 grid(E_DIM / EDGES_PER_BLOCK, B_DIM);   // (20000, 4)
    node_prop_gather_kernel<<<grid, 256>>>(ns4, src, tgt, out4);
}